// round 2
// baseline (speedup 1.0000x reference)
#include <cuda_runtime.h>

// Fixed problem shapes
#define T_TOK  4096
#define DMODEL 1024
#define NEXP   16
#define IEXP   512
#define ISH    2048
#define MAXROWS (2 * T_TOK)

// ---------------- scratch (device globals: no allocation allowed) ----------
static __device__ int   g_cnt[NEXP];
static __device__ int   g_off[NEXP + 1];
static __device__ int   g_cur[NEXP];
static __device__ int   g_rows[MAXROWS];
static __device__ float g_rwt[MAXROWS];
static __device__ int   g_eidx[T_TOK * 2];
static __device__ float g_twt[T_TOK * 2];
static __device__ float g_act_sh[(size_t)T_TOK * ISH];    // 32 MB
static __device__ float g_act_rt[(size_t)MAXROWS * IEXP]; // 16 MB

typedef unsigned long long u64;

// Packed f32x2 helpers (Blackwell FFMA2 path)
__device__ __forceinline__ u64 pk2(float lo, float hi) {
    u64 r; asm("mov.b64 %0, {%1,%2};" : "=l"(r) : "f"(lo), "f"(hi)); return r;
}
__device__ __forceinline__ void fma2(u64 &c, u64 a, u64 b) {
    asm("fma.rn.f32x2 %0, %1, %2, %0;" : "+l"(c) : "l"(a), "l"(b));
}
__device__ __forceinline__ float2 up2(u64 v) {
    float2 f; asm("mov.b64 {%0,%1}, %2;" : "=f"(f.x), "=f"(f.y) : "l"(v)); return f;
}
__device__ __forceinline__ float silu(float x) {
    return x / (1.0f + __expf(-x));
}

// ---------------- small kernels -------------------------------------------
__global__ void k_init(float* __restrict__ fused_out) {
    int i = blockIdx.x * blockDim.x + threadIdx.x;
    if (i < T_TOK * DMODEL) fused_out[i] = 0.0f;
    if (i < NEXP) g_cnt[i] = 0;
}

__global__ void k_router(const float* __restrict__ logits) {
    int t = blockIdx.x * blockDim.x + threadIdx.x;
    if (t >= T_TOK) return;
    const float* l = logits + (size_t)t * NEXP;
    float m1 = -3.4e38f, m2 = -3.4e38f;
    int i1 = 0, i2 = 0;
#pragma unroll
    for (int e = 0; e < NEXP; e++) {
        float v = l[e];
        if (v > m1) { m2 = m1; i2 = i1; m1 = v; i1 = e; }
        else if (v > m2) { m2 = v; i2 = e; }
    }
    // renormalized top-2 softmax weights: w1 = 1/(1+e^{l2-l1})
    float r   = expf(m2 - m1);
    float w2v = r / (1.0f + r);
    float w1v = 1.0f - w2v;
    g_eidx[t * 2 + 0] = i1; g_eidx[t * 2 + 1] = i2;
    g_twt [t * 2 + 0] = w1v; g_twt[t * 2 + 1] = w2v;
    atomicAdd(&g_cnt[i1], 1);
    atomicAdd(&g_cnt[i2], 1);
}

__global__ void k_prefix() {
    if (threadIdx.x == 0) {
        int s = 0;
        for (int e = 0; e < NEXP; e++) { g_off[e] = s; g_cur[e] = s; s += g_cnt[e]; }
        g_off[NEXP] = s;
    }
}

__global__ void k_scatter() {
    int t = blockIdx.x * blockDim.x + threadIdx.x;
    if (t >= T_TOK) return;
#pragma unroll
    for (int k = 0; k < 2; k++) {
        int e = g_eidx[t * 2 + k];
        int pos = atomicAdd(&g_cur[e], 1);
        g_rows[pos] = t;
        g_rwt[pos]  = g_twt[t * 2 + k];
    }
}

// ---------------- SwiGLU GEMM ----------------------------------------------
// ACT[r, n] = silu(X@Wg^T) * (X@Wu^T)
// Block tile: 128 rows x 128 gate cols (+128 paired up cols), K-slice 16.
// 256 threads, per-thread 8 rows x 8 gate + 8 up cols, FFMA2, swizzled smem,
// register-prefetched global loads.
template <bool ROUTED>
__global__ __launch_bounds__(256) void k_swiglu(const float* __restrict__ X,
                                                const float* __restrict__ W13) {
    const int NI = ROUTED ? IEXP : ISH;
    int r0, r1;
    const float* Wg;
    if (ROUTED) {
        int e  = blockIdx.x >> 5;          // / 32 m-tiles
        int mt = blockIdx.x & 31;
        r0 = g_off[e] + mt * 128;
        int re = g_off[e + 1];
        if (r0 >= re) return;
        r1 = min(re, r0 + 128);
        Wg = W13 + (size_t)e * (2 * IEXP) * DMODEL;
    } else {
        r0 = blockIdx.x * 128; r1 = r0 + 128;
        Wg = W13;
    }
    const float* Wu = Wg + (size_t)NI * DMODEL;
    const int n0 = blockIdx.y * 128;

    __shared__ float As[16][128], Bg[16][128], Bu[16][128];

    const int tid = threadIdx.x;
    const int tr  = tid & 15;       // row group: rows tr*8..tr*8+7
    const int tc  = tid >> 4;       // col group: gate cols tc*8..tc*8+7
    // loader: each thread loads rows lr0 and lr0+64, k-chunk lk..lk+3
    const int lr0 = tid >> 2;
    const int lr1 = lr0 + 64;
    const int lkq = tid & 3;
    const int lk  = lkq * 4;
    const int sw  = lkq << 3;       // store swizzle
    const int c0  = lr0 ^ sw, c1 = lr1 ^ sw;

    int ga0 = r0 + lr0, ga1 = r0 + lr1;
    if (ROUTED) { ga0 = g_rows[min(ga0, r1 - 1)]; ga1 = g_rows[min(ga1, r1 - 1)]; }
    const float* pA0 = X  + (size_t)ga0 * DMODEL + lk;
    const float* pA1 = X  + (size_t)ga1 * DMODEL + lk;
    const float* pG0 = Wg + (size_t)(n0 + lr0) * DMODEL + lk;
    const float* pG1 = Wg + (size_t)(n0 + lr1) * DMODEL + lk;
    const float* pU0 = Wu + (size_t)(n0 + lr0) * DMODEL + lk;
    const float* pU1 = Wu + (size_t)(n0 + lr1) * DMODEL + lk;

    u64 cg[8][4] = {}, cu[8][4] = {};

    float4 va0 = *(const float4*)pA0, va1 = *(const float4*)pA1;
    float4 vg0 = *(const float4*)pG0, vg1 = *(const float4*)pG1;
    float4 vu0 = *(const float4*)pU0, vu1 = *(const float4*)pU1;

    const int S = DMODEL / 16;
    for (int s = 0; s < S; s++) {
        __syncthreads();   // previous slice fully consumed
        As[lk+0][c0]=va0.x; As[lk+1][c0]=va0.y; As[lk+2][c0]=va0.z; As[lk+3][c0]=va0.w;
        As[lk+0][c1]=va1.x; As[lk+1][c1]=va1.y; As[lk+2][c1]=va1.z; As[lk+3][c1]=va1.w;
        Bg[lk+0][c0]=vg0.x; Bg[lk+1][c0]=vg0.y; Bg[lk+2][c0]=vg0.z; Bg[lk+3][c0]=vg0.w;
        Bg[lk+0][c1]=vg1.x; Bg[lk+1][c1]=vg1.y; Bg[lk+2][c1]=vg1.z; Bg[lk+3][c1]=vg1.w;
        Bu[lk+0][c0]=vu0.x; Bu[lk+1][c0]=vu0.y; Bu[lk+2][c0]=vu0.z; Bu[lk+3][c0]=vu0.w;
        Bu[lk+0][c1]=vu1.x; Bu[lk+1][c1]=vu1.y; Bu[lk+2][c1]=vu1.z; Bu[lk+3][c1]=vu1.w;
        __syncthreads();
        if (s + 1 < S) {   // prefetch next slice into registers (latency hidden)
            int off = (s + 1) * 16;
            va0 = *(const float4*)(pA0 + off); va1 = *(const float4*)(pA1 + off);
            vg0 = *(const float4*)(pG0 + off); vg1 = *(const float4*)(pG1 + off);
            vu0 = *(const float4*)(pU0 + off); vu1 = *(const float4*)(pU1 + off);
        }
#pragma unroll
        for (int k = 0; k < 16; k++) {
            const int xk = (k >> 2) << 3;
            const int ab = (tr * 8) ^ xk;
            const int bb = (tc * 8) ^ xk;
            const float4 a0 = *(const float4*)&As[k][ab];
            const float4 a1 = *(const float4*)&As[k][ab + 4];
            const ulonglong2 g0 = *(const ulonglong2*)&Bg[k][bb];
            const ulonglong2 g1 = *(const ulonglong2*)&Bg[k][bb + 4];
            const ulonglong2 u0 = *(const ulonglong2*)&Bu[k][bb];
            const ulonglong2 u1 = *(const ulonglong2*)&Bu[k][bb + 4];
            u64 ap[8];
            ap[0]=pk2(a0.x,a0.x); ap[1]=pk2(a0.y,a0.y); ap[2]=pk2(a0.z,a0.z); ap[3]=pk2(a0.w,a0.w);
            ap[4]=pk2(a1.x,a1.x); ap[5]=pk2(a1.y,a1.y); ap[6]=pk2(a1.z,a1.z); ap[7]=pk2(a1.w,a1.w);
            u64 bg[4] = {g0.x, g0.y, g1.x, g1.y};
            u64 bu[4] = {u0.x, u0.y, u1.x, u1.y};
#pragma unroll
            for (int r = 0; r < 8; r++) {
#pragma unroll
                for (int j = 0; j < 4; j++) {
                    fma2(cg[r][j], ap[r], bg[j]);
                    fma2(cu[r][j], ap[r], bu[j]);
                }
            }
        }
    }

    float* actbase = ROUTED ? g_act_rt : g_act_sh;
#pragma unroll
    for (int r = 0; r < 8; r++) {
        int row = r0 + tr * 8 + r;
        if (ROUTED && row >= r1) break;
        float* dst = actbase + (size_t)row * NI + n0 + tc * 8;
        float o[8];
#pragma unroll
        for (int j = 0; j < 4; j++) {
            float2 g = up2(cg[r][j]);
            float2 u = up2(cu[r][j]);
            o[2*j+0] = silu(g.x) * u.x;
            o[2*j+1] = silu(g.y) * u.y;
        }
        *(float4*)(dst)     = make_float4(o[0], o[1], o[2], o[3]);
        *(float4*)(dst + 4) = make_float4(o[4], o[5], o[6], o[7]);
    }
}

// ---------------- Down-proj GEMM -------------------------------------------
// OUT[tok, n] (+)= w * ACT @ W2^T
// Block tile: 128 rows x 256 cols, K-slice 16. 256 threads, per-thread 8x16.
template <bool ROUTED>
__global__ __launch_bounds__(256) void k_down(const float* __restrict__ W2,
                                              float* __restrict__ OUT) {
    const int KI = ROUTED ? IEXP : ISH;
    const float* ACT = ROUTED ? g_act_rt : g_act_sh;
    int r0, r1;
    const float* W;
    if (ROUTED) {
        int e  = blockIdx.x >> 5;
        int mt = blockIdx.x & 31;
        r0 = g_off[e] + mt * 128;
        int re = g_off[e + 1];
        if (r0 >= re) return;
        r1 = min(re, r0 + 128);
        W = W2 + (size_t)e * DMODEL * IEXP;
    } else {
        r0 = blockIdx.x * 128; r1 = r0 + 128;
        W = W2;
    }
    const int n0 = blockIdx.y * 256;

    __shared__ float As[16][128], Bs[16][256];

    const int tid = threadIdx.x;
    const int tr  = tid & 15;       // rows tr*8..+7
    const int tc  = tid >> 4;       // cols tc*16..+15
    const int lr0 = tid >> 2;
    const int lkq = tid & 3;
    const int lk  = lkq * 4;
    const int sw  = lkq << 3;
    const int ca0 = lr0 ^ sw, ca1 = (lr0 + 64) ^ sw;
    const int cb0 = ca0, cb1 = ca1, cb2 = (lr0 + 128) ^ sw, cb3 = (lr0 + 192) ^ sw;

    const float* pA0 = ACT + (size_t)min(r0 + lr0,      r1 - 1) * KI + lk;
    const float* pA1 = ACT + (size_t)min(r0 + lr0 + 64, r1 - 1) * KI + lk;
    const float* pB0 = W + (size_t)(n0 + lr0)       * KI + lk;
    const float* pB1 = W + (size_t)(n0 + lr0 + 64)  * KI + lk;
    const float* pB2 = W + (size_t)(n0 + lr0 + 128) * KI + lk;
    const float* pB3 = W + (size_t)(n0 + lr0 + 192) * KI + lk;

    u64 c[8][8] = {};

    float4 va0 = *(const float4*)pA0, va1 = *(const float4*)pA1;
    float4 vb0 = *(const float4*)pB0, vb1 = *(const float4*)pB1;
    float4 vb2 = *(const float4*)pB2, vb3 = *(const float4*)pB3;

    const int S = KI / 16;
    for (int s = 0; s < S; s++) {
        __syncthreads();
        As[lk+0][ca0]=va0.x; As[lk+1][ca0]=va0.y; As[lk+2][ca0]=va0.z; As[lk+3][ca0]=va0.w;
        As[lk+0][ca1]=va1.x; As[lk+1][ca1]=va1.y; As[lk+2][ca1]=va1.z; As[lk+3][ca1]=va1.w;
        Bs[lk+0][cb0]=vb0.x; Bs[lk+1][cb0]=vb0.y; Bs[lk+2][cb0]=vb0.z; Bs[lk+3][cb0]=vb0.w;
        Bs[lk+0][cb1]=vb1.x; Bs[lk+1][cb1]=vb1.y; Bs[lk+2][cb1]=vb1.z; Bs[lk+3][cb1]=vb1.w;
        Bs[lk+0][cb2]=vb2.x; Bs[lk+1][cb2]=vb2.y; Bs[lk+2][cb2]=vb2.z; Bs[lk+3][cb2]=vb2.w;
        Bs[lk+0][cb3]=vb3.x; Bs[lk+1][cb3]=vb3.y; Bs[lk+2][cb3]=vb3.z; Bs[lk+3][cb3]=vb3.w;
        __syncthreads();
        if (s + 1 < S) {
            int off = (s + 1) * 16;
            va0 = *(const float4*)(pA0 + off); va1 = *(const float4*)(pA1 + off);
            vb0 = *(const float4*)(pB0 + off); vb1 = *(const float4*)(pB1 + off);
            vb2 = *(const float4*)(pB2 + off); vb3 = *(const float4*)(pB3 + off);
        }
#pragma unroll
        for (int k = 0; k < 16; k++) {
            const int xk = (k >> 2) << 3;
            const int ab = (tr * 8) ^ xk;
            const float4 a0 = *(const float4*)&As[k][ab];
            const float4 a1 = *(const float4*)&As[k][ab + 4];
            u64 bv[8];
#pragma unroll
            for (int q = 0; q < 4; q++) {
                const ulonglong2 b = *(const ulonglong2*)&Bs[k][(tc * 16 + q * 4) ^ xk];
                bv[2*q]   = b.x;
                bv[2*q+1] = b.y;
            }
            u64 ap[8];
            ap[0]=pk2(a0.x,a0.x); ap[1]=pk2(a0.y,a0.y); ap[2]=pk2(a0.z,a0.z); ap[3]=pk2(a0.w,a0.w);
            ap[4]=pk2(a1.x,a1.x); ap[5]=pk2(a1.y,a1.y); ap[6]=pk2(a1.z,a1.z); ap[7]=pk2(a1.w,a1.w);
#pragma unroll
            for (int r = 0; r < 8; r++) {
#pragma unroll
                for (int j = 0; j < 8; j++) {
                    fma2(c[r][j], ap[r], bv[j]);
                }
            }
        }
    }

#pragma unroll
    for (int r = 0; r < 8; r++) {
        int row = r0 + tr * 8 + r;
        if (ROUTED && row >= r1) break;
        if (!ROUTED) {
            float* dst = OUT + (size_t)row * DMODEL + n0 + tc * 16;
#pragma unroll
            for (int q = 0; q < 4; q++) {
                float2 f0 = up2(c[r][2*q]), f1 = up2(c[r][2*q+1]);
                *(float4*)(dst + q * 4) = make_float4(f0.x, f0.y, f1.x, f1.y);
            }
        } else {
            int tok = g_rows[row];
            float w = g_rwt[row];
            float* dst = OUT + (size_t)tok * DMODEL + n0 + tc * 16;
#pragma unroll
            for (int j = 0; j < 8; j++) {
                float2 f = up2(c[r][j]);
                atomicAdd(dst + 2*j + 0, w * f.x);
                atomicAdd(dst + 2*j + 1, w * f.y);
            }
        }
    }
}

// ---------------- launch ---------------------------------------------------
extern "C" void kernel_launch(void* const* d_in, const int* in_sizes, int n_in,
                              void* d_out, int out_size) {
    const float* x      = (const float*)d_in[0]; // [T, D]
    const float* logits = (const float*)d_in[1]; // [T, E]
    const float* w13    = (const float*)d_in[2]; // [E, 2I, D]
    const float* w2     = (const float*)d_in[3]; // [E, D, I]
    const float* w13s   = (const float*)d_in[4]; // [2SI, D]
    const float* w2s    = (const float*)d_in[5]; // [D, SI]
    float* out = (float*)d_out;
    float* shared_out = out;                          // [T, D]
    float* fused_out  = out + (size_t)T_TOK * DMODEL; // [T, D]

    // routing + gather
    k_init<<<(T_TOK * DMODEL + 255) / 256, 256>>>(fused_out);
    k_router<<<(T_TOK + 255) / 256, 256>>>(logits);
    k_prefix<<<1, 32>>>();
    k_scatter<<<(T_TOK + 255) / 256, 256>>>();

    // shared expert path
    {
        dim3 g(T_TOK / 128, ISH / 128);       // 32 x 16
        k_swiglu<false><<<g, 256>>>(x, w13s);
    }
    {
        dim3 g(T_TOK / 128, DMODEL / 256);    // 32 x 4
        k_down<false><<<g, 256>>>(w2s, shared_out);
    }

    // routed experts path
    {
        dim3 g(NEXP * (T_TOK / 128), IEXP / 128);   // 512 x 4
        k_swiglu<true><<<g, 256>>>(x, w13);
    }
    {
        dim3 g(NEXP * (T_TOK / 128), DMODEL / 256); // 512 x 4
        k_down<true><<<g, 256>>>(w2, fused_out);
    }
}

// round 7
// speedup vs baseline: 2.2780x; 2.2780x over previous
#include <cuda_runtime.h>
#include <cuda_bf16.h>
#include <cstdint>

// Fixed problem shapes
#define T_TOK  4096
#define DMODEL 1024
#define NEXP   16
#define IEXP   512
#define ISH    2048
#define MAXROWS (2 * T_TOK)

typedef unsigned long long u64;

// ---------------- scratch (device globals; no allocation allowed) ----------
static __device__ int   g_cnt[NEXP];
static __device__ int   g_off[NEXP + 1];
static __device__ int   g_cur[NEXP];
static __device__ int   g_rows[MAXROWS];
static __device__ float g_rwt[MAXROWS];
static __device__ int   g_eidx[T_TOK * 2];
static __device__ float g_twt[T_TOK * 2];

// bf16 hi/lo split operands
static __device__ __nv_bfloat16 g_xh[(size_t)T_TOK * DMODEL];
static __device__ __nv_bfloat16 g_xl[(size_t)T_TOK * DMODEL];
static __device__ __nv_bfloat16 g_w13h[(size_t)NEXP * 2 * IEXP * DMODEL];
static __device__ __nv_bfloat16 g_w13l[(size_t)NEXP * 2 * IEXP * DMODEL];
static __device__ __nv_bfloat16 g_w2h[(size_t)NEXP * DMODEL * IEXP];
static __device__ __nv_bfloat16 g_w2l[(size_t)NEXP * DMODEL * IEXP];
static __device__ __nv_bfloat16 g_w13sh[(size_t)2 * ISH * DMODEL];
static __device__ __nv_bfloat16 g_w13sl[(size_t)2 * ISH * DMODEL];
static __device__ __nv_bfloat16 g_w2sh[(size_t)DMODEL * ISH];
static __device__ __nv_bfloat16 g_w2sl[(size_t)DMODEL * ISH];
// activations (hi/lo)
static __device__ __nv_bfloat16 g_acth[(size_t)T_TOK * ISH];
static __device__ __nv_bfloat16 g_actl[(size_t)T_TOK * ISH];
static __device__ __nv_bfloat16 g_arth[(size_t)MAXROWS * IEXP];
static __device__ __nv_bfloat16 g_artl[(size_t)MAXROWS * IEXP];

// ---------------- PTX helpers ----------------------------------------------
__device__ __forceinline__ uint32_t smem_u32(const void* p) {
    uint32_t a;
    asm("{ .reg .u64 t; cvta.to.shared.u64 t, %1; cvt.u32.u64 %0, t; }" : "=r"(a) : "l"(p));
    return a;
}
__device__ __forceinline__ void cpa16(uint32_t s, const void* g) {
    asm volatile("cp.async.cg.shared.global [%0], [%1], 16;" :: "r"(s), "l"(g) : "memory");
}
__device__ __forceinline__ void cpa_commit() {
    asm volatile("cp.async.commit_group;" ::: "memory");
}
template <int N>
__device__ __forceinline__ void cpa_wait() {
    asm volatile("cp.async.wait_group %0;" :: "n"(N) : "memory");
}
__device__ __forceinline__ void ldsm4(uint32_t* r, uint32_t addr) {
    asm volatile("ldmatrix.sync.aligned.m8n8.x4.shared.b16 {%0,%1,%2,%3}, [%4];"
        : "=r"(r[0]), "=r"(r[1]), "=r"(r[2]), "=r"(r[3]) : "r"(addr));
}
__device__ __forceinline__ void mma16816(float* d, const uint32_t* a, const uint32_t* b) {
    asm volatile(
        "mma.sync.aligned.m16n8k16.row.col.f32.bf16.bf16.f32 "
        "{%0,%1,%2,%3}, {%4,%5,%6,%7}, {%8,%9}, {%0,%1,%2,%3};"
        : "+f"(d[0]), "+f"(d[1]), "+f"(d[2]), "+f"(d[3])
        : "r"(a[0]), "r"(a[1]), "r"(a[2]), "r"(a[3]), "r"(b[0]), "r"(b[1]));
}
__device__ __forceinline__ uint32_t swz(uint32_t bo) { return bo ^ ((bo >> 3) & 0x70); }
__device__ __forceinline__ float silu(float x) { return x / (1.0f + __expf(-x)); }

// ---------------- small kernels -------------------------------------------
__global__ void k_init(float* __restrict__ fused_out) {
    int i = blockIdx.x * blockDim.x + threadIdx.x;
    if (i < T_TOK * DMODEL) fused_out[i] = 0.0f;
    if (i < NEXP) g_cnt[i] = 0;
}

__global__ void k_router(const float* __restrict__ logits) {
    int t = blockIdx.x * blockDim.x + threadIdx.x;
    if (t >= T_TOK) return;
    const float* l = logits + (size_t)t * NEXP;
    float m1 = -3.4e38f, m2 = -3.4e38f;
    int i1 = 0, i2 = 0;
#pragma unroll
    for (int e = 0; e < NEXP; e++) {
        float v = l[e];
        if (v > m1) { m2 = m1; i2 = i1; m1 = v; i1 = e; }
        else if (v > m2) { m2 = v; i2 = e; }
    }
    float r   = expf(m2 - m1);
    float w2v = r / (1.0f + r);
    float w1v = 1.0f - w2v;
    g_eidx[t * 2 + 0] = i1; g_eidx[t * 2 + 1] = i2;
    g_twt [t * 2 + 0] = w1v; g_twt[t * 2 + 1] = w2v;
    atomicAdd(&g_cnt[i1], 1);
    atomicAdd(&g_cnt[i2], 1);
}

__global__ void k_prefix() {
    if (threadIdx.x == 0) {
        int s = 0;
        for (int e = 0; e < NEXP; e++) { g_off[e] = s; g_cur[e] = s; s += g_cnt[e]; }
        g_off[NEXP] = s;
    }
}

__global__ void k_scatter() {
    int t = blockIdx.x * blockDim.x + threadIdx.x;
    if (t >= T_TOK) return;
#pragma unroll
    for (int k = 0; k < 2; k++) {
        int e = g_eidx[t * 2 + k];
        int pos = atomicAdd(&g_cur[e], 1);
        g_rows[pos] = t;
        g_rwt[pos]  = g_twt[t * 2 + k];
    }
}

// fp32 -> bf16 hi/lo split (vectorized)
__global__ void k_cvt4(const float4* __restrict__ s, uint2* __restrict__ h,
                       uint2* __restrict__ l, int n4) {
    int i = blockIdx.x * blockDim.x + threadIdx.x;
    if (i >= n4) return;
    float4 v = s[i];
    __nv_bfloat16 h0 = __float2bfloat16(v.x), h1 = __float2bfloat16(v.y);
    __nv_bfloat16 h2 = __float2bfloat16(v.z), h3 = __float2bfloat16(v.w);
    __nv_bfloat16 l0 = __float2bfloat16(v.x - __bfloat162float(h0));
    __nv_bfloat16 l1 = __float2bfloat16(v.y - __bfloat162float(h1));
    __nv_bfloat16 l2 = __float2bfloat16(v.z - __bfloat162float(h2));
    __nv_bfloat16 l3 = __float2bfloat16(v.w - __bfloat162float(h3));
    __nv_bfloat162 hp0{h0, h1}, hp1{h2, h3}, lp0{l0, l1}, lp1{l2, l3};
    uint2 hh, ll;
    hh.x = *(uint32_t*)&hp0; hh.y = *(uint32_t*)&hp1;
    ll.x = *(uint32_t*)&lp0; ll.y = *(uint32_t*)&lp1;
    h[i] = hh; l[i] = ll;
}

// ---------------- SwiGLU HMMA GEMM -----------------------------------------
// Block: 128 token rows x 64 gate cols + 64 up cols. K-stage 64, double buffer.
// Warps 0-3: gate (32 rows each); warps 4-7: up (same rows).
// 3 passes: Ah*Bh + Ah*Bl + Al*Bh.
#define SW_STAGE 65536      // Ah 16K | Al 16K | Gh 8K | Gl 8K | Uh 8K | Ul 8K
template <bool ROUTED>
__global__ __launch_bounds__(256) void k_swiglu_mma() {
    extern __shared__ char smem[];
    const int NI = ROUTED ? IEXP : ISH;
    int r0, r1;
    const __nv_bfloat16 *Wh, *Wl;
    if (ROUTED) {
        int e = blockIdx.x >> 5, mt = blockIdx.x & 31;
        r0 = g_off[e] + mt * 128;
        int re = g_off[e + 1];
        if (r0 >= re) return;
        r1 = min(re, r0 + 128);
        Wh = g_w13h + (size_t)e * 2 * IEXP * DMODEL;
        Wl = g_w13l + (size_t)e * 2 * IEXP * DMODEL;
    } else {
        r0 = blockIdx.x * 128; r1 = r0 + 128;
        Wh = g_w13sh; Wl = g_w13sl;
    }
    const int n0  = blockIdx.y * 64;
    const int tid = threadIdx.x, wid = tid >> 5, lid = tid & 31;
    const int wm = wid & 3, isup = wid >> 2;
    uint32_t sb = smem_u32(smem);

    // loader precompute
    const int lrow = tid >> 3, v = tid & 7;
    uint32_t soA[4]; size_t aofh[4];
#pragma unroll
    for (int j = 0; j < 4; j++) {
        int rr = lrow + 32 * j;
        soA[j] = swz((uint32_t)(rr * 128 + v * 16));
        int ar = r0 + rr;
        if (ROUTED) ar = g_rows[min(ar, r1 - 1)];
        aofh[j] = (size_t)ar * DMODEL + v * 8;
    }
    uint32_t soB[2]; size_t gof[2], uof[2];
#pragma unroll
    for (int j = 0; j < 2; j++) {
        int rr = lrow + 32 * j;
        soB[j] = swz((uint32_t)(rr * 128 + v * 16));
        gof[j] = (size_t)(n0 + rr) * DMODEL + v * 8;
        uof[j] = (size_t)(NI + n0 + rr) * DMODEL + v * 8;
    }

    float acc[2][8][4];
#pragma unroll
    for (int a = 0; a < 2; a++)
#pragma unroll
        for (int b = 0; b < 8; b++)
#pragma unroll
            for (int c = 0; c < 4; c++) acc[a][b][c] = 0.0f;

    const int S = DMODEL / 64;   // 16

#define SW_ISSUE(stg)                                                          \
    {                                                                          \
        uint32_t tb = sb + ((stg) & 1) * SW_STAGE;                             \
        int kof = (stg) * 64;                                                  \
        _Pragma("unroll")                                                      \
        for (int j = 0; j < 4; j++) {                                          \
            cpa16(tb +     0 + soA[j], g_xh + aofh[j] + kof);                  \
            cpa16(tb + 16384 + soA[j], g_xl + aofh[j] + kof);                  \
        }                                                                      \
        _Pragma("unroll")                                                      \
        for (int j = 0; j < 2; j++) {                                          \
            cpa16(tb + 32768 + soB[j], Wh + gof[j] + kof);                     \
            cpa16(tb + 40960 + soB[j], Wl + gof[j] + kof);                     \
            cpa16(tb + 49152 + soB[j], Wh + uof[j] + kof);                     \
            cpa16(tb + 57344 + soB[j], Wl + uof[j] + kof);                     \
        }                                                                      \
        cpa_commit();                                                          \
    }

    SW_ISSUE(0);
    for (int s = 0; s < S; s++) {
        if (s + 1 < S) { SW_ISSUE(s + 1); cpa_wait<1>(); }
        else            cpa_wait<0>();
        __syncthreads();
        uint32_t tb = sb + (s & 1) * SW_STAGE;
        uint32_t sA = tb;
        uint32_t sB = tb + 32768 + isup * 16384;
#pragma unroll
        for (int ks = 0; ks < 4; ks++) {
            int kb = ks * 32;
            uint32_t ah[2][4], al[2][4];
#pragma unroll
            for (int mt = 0; mt < 2; mt++) {
                int row = wm * 32 + mt * 16 + (lid & 15);
                uint32_t bo = (uint32_t)(row * 128 + kb + ((lid >> 4) << 4));
                uint32_t ad = sA + (bo ^ ((row & 7) << 4));
                ldsm4(ah[mt], ad);
                ldsm4(al[mt], ad + 16384);
            }
#pragma unroll
            for (int ng = 0; ng < 4; ng++) {
                int nrow = ng * 16 + (lid & 7) + ((lid >> 4) << 3);
                uint32_t bo = (uint32_t)(nrow * 128 + kb + (((lid >> 3) & 1) << 4));
                uint32_t ad = sB + (bo ^ ((nrow & 7) << 4));
                uint32_t bh[4], bl[4];
                ldsm4(bh, ad);
                ldsm4(bl, ad + 8192);
#pragma unroll
                for (int mt = 0; mt < 2; mt++)
#pragma unroll
                    for (int p = 0; p < 2; p++) {
                        int nt = ng * 2 + p;
                        mma16816(acc[mt][nt], ah[mt], bh + 2 * p);
                        mma16816(acc[mt][nt], ah[mt], bl + 2 * p);
                        mma16816(acc[mt][nt], al[mt], bh + 2 * p);
                    }
            }
        }
        __syncthreads();
    }
#undef SW_ISSUE

    // epilogue: up warps stash U to smem; gate warps combine silu(g)*u
    float* u_s = (float*)smem;                            // [128][66]
    __nv_bfloat16* h_s = (__nv_bfloat16*)(smem + 34816);  // [128][72]
    __nv_bfloat16* l_s = (__nv_bfloat16*)(smem + 53248);  // [128][72]
    if (isup) {
#pragma unroll
        for (int mt = 0; mt < 2; mt++)
#pragma unroll
            for (int nt = 0; nt < 8; nt++) {
                int r_ = wm * 32 + mt * 16 + (lid >> 2);
                int c_ = nt * 8 + 2 * (lid & 3);
                *(float2*)&u_s[r_ * 66 + c_]       = make_float2(acc[mt][nt][0], acc[mt][nt][1]);
                *(float2*)&u_s[(r_ + 8) * 66 + c_] = make_float2(acc[mt][nt][2], acc[mt][nt][3]);
            }
    }
    __syncthreads();
    if (!isup) {
#pragma unroll
        for (int mt = 0; mt < 2; mt++)
#pragma unroll
            for (int nt = 0; nt < 8; nt++) {
                int r_ = wm * 32 + mt * 16 + (lid >> 2);
                int c_ = nt * 8 + 2 * (lid & 3);
#pragma unroll
                for (int hh = 0; hh < 2; hh++) {
                    int rr = r_ + hh * 8;
                    float2 u = *(float2*)&u_s[rr * 66 + c_];
                    float o0 = silu(acc[mt][nt][2 * hh + 0]) * u.x;
                    float o1 = silu(acc[mt][nt][2 * hh + 1]) * u.y;
                    __nv_bfloat16 h0 = __float2bfloat16(o0), h1 = __float2bfloat16(o1);
                    __nv_bfloat16 q0 = __float2bfloat16(o0 - __bfloat162float(h0));
                    __nv_bfloat16 q1 = __float2bfloat16(o1 - __bfloat162float(h1));
                    __nv_bfloat162 hp{h0, h1}, lp{q0, q1};
                    *(uint32_t*)&h_s[rr * 72 + c_] = *(uint32_t*)&hp;
                    *(uint32_t*)&l_s[rr * 72 + c_] = *(uint32_t*)&lp;
                }
            }
    }
    __syncthreads();
    __nv_bfloat16* AH = ROUTED ? g_arth : g_acth;
    __nv_bfloat16* AL = ROUTED ? g_artl : g_actl;
    for (int i = tid; i < 128 * 8; i += 256) {
        int row = i >> 3, vv = i & 7;
        if (ROUTED && r0 + row >= r1) continue;
        *(uint4*)(AH + (size_t)(r0 + row) * NI + n0 + vv * 8) = *(uint4*)(h_s + row * 72 + vv * 8);
        *(uint4*)(AL + (size_t)(r0 + row) * NI + n0 + vv * 8) = *(uint4*)(l_s + row * 72 + vv * 8);
    }
}

// ---------------- Down-proj HMMA GEMM ---------------------------------------
// Block: 128 rows x 128 cols, K-stage 64 over KI, double buffer. Warps 4x2.
#define DN_STAGE 65536      // Ah 16K | Al 16K | Bh 16K | Bl 16K
template <bool ROUTED>
__global__ __launch_bounds__(256) void k_down_mma(float* __restrict__ OUT) {
    extern __shared__ char smem[];
    const int KI = ROUTED ? IEXP : ISH;
    const __nv_bfloat16* AHs = ROUTED ? g_arth : g_acth;
    const __nv_bfloat16* ALs = ROUTED ? g_artl : g_actl;
    int r0, r1;
    const __nv_bfloat16 *Wh, *Wl;
    if (ROUTED) {
        int e = blockIdx.x >> 5, mt = blockIdx.x & 31;
        r0 = g_off[e] + mt * 128;
        int re = g_off[e + 1];
        if (r0 >= re) return;
        r1 = min(re, r0 + 128);
        Wh = g_w2h + (size_t)e * DMODEL * IEXP;
        Wl = g_w2l + (size_t)e * DMODEL * IEXP;
    } else {
        r0 = blockIdx.x * 128; r1 = r0 + 128;
        Wh = g_w2sh; Wl = g_w2sl;
    }
    const int n0  = blockIdx.y * 128;
    const int tid = threadIdx.x, wid = tid >> 5, lid = tid & 31;
    const int wm = wid & 3, wn = wid >> 2;
    uint32_t sb = smem_u32(smem);

    const int lrow = tid >> 3, v = tid & 7;
    uint32_t so[4]; size_t aof[4], bof[4];
#pragma unroll
    for (int j = 0; j < 4; j++) {
        int rr = lrow + 32 * j;
        so[j]  = swz((uint32_t)(rr * 128 + v * 16));
        aof[j] = (size_t)min(r0 + rr, r1 - 1) * KI + v * 8;
        bof[j] = (size_t)(n0 + rr) * KI + v * 8;
    }

    float acc[2][8][4];
#pragma unroll
    for (int a = 0; a < 2; a++)
#pragma unroll
        for (int b = 0; b < 8; b++)
#pragma unroll
            for (int c = 0; c < 4; c++) acc[a][b][c] = 0.0f;

    const int S = KI / 64;

#define DN_ISSUE(stg)                                                          \
    {                                                                          \
        uint32_t tb = sb + ((stg) & 1) * DN_STAGE;                             \
        int kof = (stg) * 64;                                                  \
        _Pragma("unroll")                                                      \
        for (int j = 0; j < 4; j++) {                                          \
            cpa16(tb +     0 + so[j], AHs + aof[j] + kof);                     \
            cpa16(tb + 16384 + so[j], ALs + aof[j] + kof);                     \
            cpa16(tb + 32768 + so[j], Wh + bof[j] + kof);                      \
            cpa16(tb + 49152 + so[j], Wl + bof[j] + kof);                      \
        }                                                                      \
        cpa_commit();                                                          \
    }

    DN_ISSUE(0);
    for (int s = 0; s < S; s++) {
        if (s + 1 < S) { DN_ISSUE(s + 1); cpa_wait<1>(); }
        else            cpa_wait<0>();
        __syncthreads();
        uint32_t tb = sb + (s & 1) * DN_STAGE;
        uint32_t sA = tb, sB = tb + 32768;
#pragma unroll
        for (int ks = 0; ks < 4; ks++) {
            int kb = ks * 32;
            uint32_t ah[2][4], al[2][4];
#pragma unroll
            for (int mt = 0; mt < 2; mt++) {
                int row = wm * 32 + mt * 16 + (lid & 15);
                uint32_t bo = (uint32_t)(row * 128 + kb + ((lid >> 4) << 4));
                uint32_t ad = sA + (bo ^ ((row & 7) << 4));
                ldsm4(ah[mt], ad);
                ldsm4(al[mt], ad + 16384);
            }
#pragma unroll
            for (int ng = 0; ng < 4; ng++) {
                int nrow = wn * 64 + ng * 16 + (lid & 7) + ((lid >> 4) << 3);
                uint32_t bo = (uint32_t)(nrow * 128 + kb + (((lid >> 3) & 1) << 4));
                uint32_t ad = sB + (bo ^ ((nrow & 7) << 4));
                uint32_t bh[4], bl[4];
                ldsm4(bh, ad);
                ldsm4(bl, ad + 16384);
#pragma unroll
                for (int mt = 0; mt < 2; mt++)
#pragma unroll
                    for (int p = 0; p < 2; p++) {
                        int nt = ng * 2 + p;
                        mma16816(acc[mt][nt], ah[mt], bh + 2 * p);
                        mma16816(acc[mt][nt], ah[mt], bl + 2 * p);
                        mma16816(acc[mt][nt], al[mt], bh + 2 * p);
                    }
            }
        }
        __syncthreads();
    }
#undef DN_ISSUE

    // epilogue via smem f32 tile [128][132]
    float* c_s = (float*)smem;
#pragma unroll
    for (int mt = 0; mt < 2; mt++)
#pragma unroll
        for (int nt = 0; nt < 8; nt++) {
            int r_ = wm * 32 + mt * 16 + (lid >> 2);
            int c_ = wn * 64 + nt * 8 + 2 * (lid & 3);
            *(float2*)&c_s[r_ * 132 + c_]       = make_float2(acc[mt][nt][0], acc[mt][nt][1]);
            *(float2*)&c_s[(r_ + 8) * 132 + c_] = make_float2(acc[mt][nt][2], acc[mt][nt][3]);
        }
    __syncthreads();
    if (!ROUTED) {
        for (int i = tid; i < 128 * 32; i += 256) {
            int row = i >> 5, vv = i & 31;
            *(float4*)(OUT + (size_t)(r0 + row) * DMODEL + n0 + vv * 4) =
                *(float4*)(c_s + row * 132 + vv * 4);
        }
    } else {
        for (int i = tid; i < 128 * 128; i += 256) {
            int row = i >> 7, col = i & 127;
            if (r0 + row < r1) {
                int tok = g_rows[r0 + row];
                float w = g_rwt[r0 + row];
                atomicAdd(&OUT[(size_t)tok * DMODEL + n0 + col], w * c_s[row * 132 + col]);
            }
        }
    }
}

// ---------------- launch ---------------------------------------------------
extern "C" void kernel_launch(void* const* d_in, const int* in_sizes, int n_in,
                              void* d_out, int out_size) {
    const float* x      = (const float*)d_in[0];
    const float* logits = (const float*)d_in[1];
    const float* w13    = (const float*)d_in[2];
    const float* w2     = (const float*)d_in[3];
    const float* w13s   = (const float*)d_in[4];
    const float* w2s    = (const float*)d_in[5];
    float* out = (float*)d_out;
    float* shared_out = out;
    float* fused_out  = out + (size_t)T_TOK * DMODEL;

    cudaFuncSetAttribute(k_swiglu_mma<false>, cudaFuncAttributeMaxDynamicSharedMemorySize, 2 * SW_STAGE);
    cudaFuncSetAttribute(k_swiglu_mma<true>,  cudaFuncAttributeMaxDynamicSharedMemorySize, 2 * SW_STAGE);
    cudaFuncSetAttribute(k_down_mma<false>,   cudaFuncAttributeMaxDynamicSharedMemorySize, 2 * DN_STAGE);
    cudaFuncSetAttribute(k_down_mma<true>,    cudaFuncAttributeMaxDynamicSharedMemorySize, 2 * DN_STAGE);

    // routing
    k_init<<<(T_TOK * DMODEL + 255) / 256, 256>>>(fused_out);
    k_router<<<(T_TOK + 255) / 256, 256>>>(logits);
    k_prefix<<<1, 32>>>();
    k_scatter<<<(T_TOK + 255) / 256, 256>>>();

    // hi/lo conversions
    __nv_bfloat16 *xh, *xl, *w13h, *w13l, *w2h, *w2l, *w13sh, *w13sl, *w2sh, *w2sl;
    cudaGetSymbolAddress((void**)&xh, g_xh);   cudaGetSymbolAddress((void**)&xl, g_xl);
    cudaGetSymbolAddress((void**)&w13h, g_w13h); cudaGetSymbolAddress((void**)&w13l, g_w13l);
    cudaGetSymbolAddress((void**)&w2h, g_w2h);   cudaGetSymbolAddress((void**)&w2l, g_w2l);
    cudaGetSymbolAddress((void**)&w13sh, g_w13sh); cudaGetSymbolAddress((void**)&w13sl, g_w13sl);
    cudaGetSymbolAddress((void**)&w2sh, g_w2sh);   cudaGetSymbolAddress((void**)&w2sl, g_w2sl);

    auto cvt = [](const float* src, __nv_bfloat16* h, __nv_bfloat16* l, int n) {
        int n4 = n / 4;
        k_cvt4<<<(n4 + 255) / 256, 256>>>((const float4*)src, (uint2*)h, (uint2*)l, n4);
    };
    cvt(x,    xh,    xl,    T_TOK * DMODEL);
    cvt(w13s, w13sh, w13sl, 2 * ISH * DMODEL);
    cvt(w13,  w13h,  w13l,  NEXP * 2 * IEXP * DMODEL);
    cvt(w2s,  w2sh,  w2sl,  DMODEL * ISH);
    cvt(w2,   w2h,   w2l,   NEXP * DMODEL * IEXP);

    // shared swiglu
    {
        dim3 g(T_TOK / 128, ISH / 64);    // 32 x 32
        k_swiglu_mma<false><<<g, 256, 2 * SW_STAGE>>>();
    }
    // routed swiglu
    {
        dim3 g(NEXP * 32, IEXP / 64);     // 512 x 8 (early-exit empty tiles)
        k_swiglu_mma<true><<<g, 256, 2 * SW_STAGE>>>();
    }
    // shared down
    {
        dim3 g(T_TOK / 128, DMODEL / 128); // 32 x 8
        k_down_mma<false><<<g, 256, 2 * DN_STAGE>>>(shared_out);
    }
    // routed down
    {
        dim3 g(NEXP * 32, DMODEL / 128);   // 512 x 8
        k_down_mma<true><<<g, 256, 2 * DN_STAGE>>>(fused_out);
    }
}